// round 11
// baseline (speedup 1.0000x reference)
#include <cuda_runtime.h>

#define G   16
#define Bsz 2
#define C   256
#define Cg  16
#define HW  576     // 24*24
#define AC  6400    // 25*C
#define EPSI 1e-5f

typedef unsigned long long ull;

// Scratch (device globals — no allocation allowed)
__device__ float g_h1[G*Bsz*C*HW];     // (i,b,c,hw)  18.9 MB (L2-resident)
__device__ float g_pooled[G*Bsz*AC];   // (i,b,ac)
__device__ float g_aff[G*Bsz*G];       // aff_i[i,b,l]

// ---- packed f32x2 helpers (sm_103a FFMA2 path, not emitted by ptxas from C++) ----
__device__ __forceinline__ ull pack2(float lo, float hi) {
    ull r; asm("mov.b64 %0, {%1,%2};" : "=l"(r) : "f"(lo), "f"(hi)); return r;
}
__device__ __forceinline__ ull dup2(float v) {
    ull r; asm("mov.b64 %0, {%1,%1};" : "=l"(r) : "f"(v)); return r;
}
__device__ __forceinline__ void unpack2(ull v, float& lo, float& hi) {
    asm("mov.b64 {%0,%1}, %2;" : "=f"(lo), "=f"(hi) : "l"(v));
}
__device__ __forceinline__ ull fma2(ull a, ull b, ull c) {
    ull d; asm("fma.rn.f32x2 %0, %1, %2, %3;" : "=l"(d) : "l"(a), "l"(b), "l"(c));
    return d;
}
__device__ __forceinline__ ull add2(ull a, ull b) {
    ull d; asm("add.rn.f32x2 %0, %1, %2;" : "=l"(d) : "l"(a), "l"(b));
    return d;
}

// ---------------------------------------------------------------------------
// Kernel 1: 16x grouped 3x3 conv + BN + ReLU -> g_h1
// Block = (i, b, group k, oc-half h): 1024 blocks, 8 out-channels each.
// Padded 26x26 input tile (border zeroed explicitly -> single sync phase).
// 3 pixels x 8 oc per thread, oc-pairs in f32x2 halves.
// ---------------------------------------------------------------------------
__global__ __launch_bounds__(192, 4) void conv1_kernel(
    const float* __restrict__ x,  const float* __restrict__ W1,
    const float* __restrict__ g1, const float* __restrict__ b1,
    const float* __restrict__ m1, const float* __restrict__ v1)
{
    __shared__ __align__(16) float xt[16*676];        // padded 26x26, 43264 B
    __shared__ __align__(8)  float wsh[144*8];        // [(cin*9+tap)*8 + o]
    const int bid = blockIdx.x;
    const int i = bid >> 6, b = (bid >> 5) & 1, k = (bid >> 1) & 15, h = bid & 1;
    const int tid = threadIdx.x;

    // border zeros (1600 cells), interior, and weights: one phase, one sync
    for (int idx = tid; idx < 1600; idx += 192) {
        int c = idx / 100, r = idx - c*100;
        int cell;
        if      (r < 26) cell = r;                   // row 0
        else if (r < 52) cell = 25*26 + (r - 26);    // row 25
        else if (r < 76) cell = (r - 52 + 1)*26;     // col 0, rows 1..24
        else             cell = (r - 76 + 1)*26 + 25;// col 25, rows 1..24
        xt[c*676 + cell] = 0.f;
    }
    const float* xsrc = x + (b*C + k*16)*HW;          // 16 contiguous channels
    for (int idx = tid; idx < 16*HW; idx += 192) {
        int c = idx / HW, rem = idx - c*HW;
        int y = rem / 24, xx = rem - y*24;
        xt[c*676 + (y + 1)*26 + (xx + 1)] = xsrc[idx];
    }
    const float* wsrc = W1 + (i*C + k*16 + h*8)*144;  // 1152 contiguous floats
    for (int idx = tid; idx < 1152; idx += 192) {
        int o = idx / 144, r = idx - o*144;           // r = cin*9 + tap
        wsh[r*8 + o] = wsrc[idx];
    }
    __syncthreads();

    ull acc2[3][4];
    #pragma unroll
    for (int j = 0; j < 3; j++)
        #pragma unroll
        for (int op = 0; op < 4; op++) acc2[j][op] = 0ull;

    int p[3], pb[3];
    #pragma unroll
    for (int j = 0; j < 3; j++) {
        p[j] = tid + j*192;                 // all < 576
        int py = p[j] / 24, px = p[j] - py*24;
        pb[j] = py*26 + px;                 // padded base
    }

    for (int cin = 0; cin < 16; cin++) {
        const float* tc = xt + cin*676;
        #pragma unroll
        for (int dy = 0; dy < 3; dy++) {
            #pragma unroll
            for (int dx = 0; dx < 3; dx++) {
                ull xp[3];
                #pragma unroll
                for (int j = 0; j < 3; j++)
                    xp[j] = dup2(tc[pb[j] + dy*26 + dx]); // imm-offset LDS.32
                const ull* wrow = (const ull*)&wsh[(cin*9 + dy*3 + dx)*8];
                #pragma unroll
                for (int op = 0; op < 4; op++) {
                    ull wv = wrow[op];                   // broadcast LDS.64
                    #pragma unroll
                    for (int j = 0; j < 3; j++)
                        acc2[j][op] = fma2(xp[j], wv, acc2[j][op]);
                }
            }
        }
    }

    float* dst = g_h1 + ((i*Bsz + b)*C + k*16 + h*8)*HW;
    #pragma unroll
    for (int op = 0; op < 4; op++) {
        float a0[3], a1[3];
        #pragma unroll
        for (int j = 0; j < 3; j++) unpack2(acc2[j][op], a0[j], a1[j]);
        #pragma unroll
        for (int half = 0; half < 2; half++) {
            const int o = op*2 + half;
            const int pi = i*C + k*16 + h*8 + o;
            const float s  = g1[pi] * rsqrtf(v1[pi] + EPSI);
            const float cc = fmaf(-m1[pi], s, b1[pi]);
            #pragma unroll
            for (int j = 0; j < 3; j++) {
                float av = half ? a1[j] : a0[j];
                dst[o*HW + p[j]] = fmaxf(fmaf(av, s, cc), 0.f);
            }
        }
    }
}

// ---------------------------------------------------------------------------
// Kernel 2: fused 1x1 grouped conv (pad=1!) + BN + ReLU + 26x26 spatial mean.
// CHANNEL-PAIR-IN-HALVES: each lane owns ONE pixel (scalar LDS.32 -> dup2),
// f32x2 halves carry two output channels -> 8 channels per 128 weight regs.
// Crossbar: 16 LDS.32 per 4096 MACs (16 cyc) vs fma 38 cyc -> fma-bound.
// ReLU accumulation without unpack: sum(relu t) = (sum t + sum |t|)/2,
// |t| per-half = 64-bit AND with 0x7fffffff7fffffff.
// ---------------------------------------------------------------------------
__global__ __launch_bounds__(128) void conv2_pool_kernel(
    const float* __restrict__ W2, const float* __restrict__ g2,
    const float* __restrict__ b2, const float* __restrict__ m2,
    const float* __restrict__ v2)
{
    __shared__ float tile[16*HW];     // 36 KB
    const int bid = blockIdx.x;
    const int i = bid >> 6, b = (bid >> 5) & 1, k = (bid >> 1) & 15, hh = bid & 1;
    const int tid = threadIdx.x, lane = tid & 31, warp = tid >> 5;

    const float* src = g_h1 + ((i*Bsz + b)*C + k*16)*HW;  // contiguous 9216 floats
    for (int idx = tid; idx < 16*HW; idx += 128) tile[idx] = src[idx];
    __syncthreads();

    float* pooled = g_pooled + (i*Bsz + b)*AC + k*400;
    const ull ABSM = 0x7fffffff7fffffffULL;

    // 25 groups of 8 channels in this half; warps take groups round-robin
    for (int grp = warp; grp < 25; grp += 4) {
        const int cb = hh*200 + grp*8;          // first of 8 channels
        ull w2[4][16], s2[4], c2[4];
        float cj[8];
        #pragma unroll
        for (int j = 0; j < 4; j++) {
            const int pi0 = i*AC + k*400 + cb + 2*j;
            const int pi1 = pi0 + 1;
            const float* wp0 = W2 + pi0*16;
            const float* wp1 = W2 + pi1*16;
            #pragma unroll
            for (int cin = 0; cin < 16; cin++)
                w2[j][cin] = pack2(wp0[cin], wp1[cin]);
            float sc0 = g2[pi0] * rsqrtf(v2[pi0] + EPSI);
            float sc1 = g2[pi1] * rsqrtf(v2[pi1] + EPSI);
            float cc0 = fmaf(-m2[pi0], sc0, b2[pi0]);
            float cc1 = fmaf(-m2[pi1], sc1, b2[pi1]);
            cj[2*j] = cc0; cj[2*j+1] = cc1;
            s2[j] = pack2(sc0, sc1);
            c2[j] = pack2(cc0, cc1);
        }

        ull acc_s[4] = {0,0,0,0}, acc_a[4] = {0,0,0,0};
        #pragma unroll 1
        for (int it = 0; it < 18; it++) {              // 576 pixels / 32 lanes
            const float* tp = tile + (lane + it*32);
            ull d2[4] = {0,0,0,0};
            #pragma unroll
            for (int cin = 0; cin < 16; cin++) {
                ull xp = dup2(tp[cin*HW]);             // LDS.32 + dup, no conflicts
                #pragma unroll
                for (int j = 0; j < 4; j++)
                    d2[j] = fma2(xp, w2[j][cin], d2[j]);
            }
            #pragma unroll
            for (int j = 0; j < 4; j++) {
                ull t = fma2(d2[j], s2[j], c2[j]);     // BN, both channels
                acc_s[j] = add2(acc_s[j], t);
                acc_a[j] = add2(acc_a[j], t & ABSM);   // |t| per half
            }
        }
        #pragma unroll
        for (int j = 0; j < 4; j++) {
            float slo, shi, alo, ahi;
            unpack2(acc_s[j], slo, shi);
            unpack2(acc_a[j], alo, ahi);
            float r0 = 0.5f*(slo + alo);               // sum relu, channel 2j
            float r1 = 0.5f*(shi + ahi);               // channel 2j+1
            #pragma unroll
            for (int off = 16; off; off >>= 1) {
                r0 += __shfl_xor_sync(0xffffffffu, r0, off);
                r1 += __shfl_xor_sync(0xffffffffu, r1, off);
            }
            if (lane == 0) {
                float bo0 = 100.f * fmaxf(cj[2*j],   0.f);
                float bo1 = 100.f * fmaxf(cj[2*j+1], 0.f);
                pooled[cb + 2*j]     = (r0 + bo0) * (1.f / 676.f);
                pooled[cb + 2*j + 1] = (r1 + bo1) * (1.f / 676.f);
            }
        }
    }
}

// ---------------------------------------------------------------------------
// aff_i[i,b,l] = <pooled[i,b,i*400:..], pooled[i,b,l*400:..]>/16
// One warp per (i,b,l).
// ---------------------------------------------------------------------------
__global__ __launch_bounds__(256) void aff_kernel()
{
    const int gw = blockIdx.x*8 + (threadIdx.x >> 5);   // 0..511
    const int lane = threadIdx.x & 31;
    const int i = gw >> 5, b = (gw >> 4) & 1, l = gw & 15;
    const float* base = g_pooled + (i*Bsz + b)*AC;
    const float* pa = base + i*400;
    const float* pb = base + l*400;
    float s = 0.f;
    #pragma unroll
    for (int m3 = lane; m3 < 400; m3 += 32)
        s = fmaf(pa[m3], pb[m3], s);
    #pragma unroll
    for (int off = 16; off; off >>= 1)
        s += __shfl_xor_sync(0xffffffffu, s, off);
    if (lane == 0) g_aff[(i*Bsz + b)*G + l] = s * (1.f / 16.f);
}

// ---------------------------------------------------------------------------
// z[i,p,q,cg,hw] = sum_k aff_i[i,p,k] * h1[i,q,k*16+cg,hw]
// float4 pixel quads; each thread produces both p outputs from one h1 read.
// ---------------------------------------------------------------------------
__global__ __launch_bounds__(256) void out_kernel(float4* __restrict__ out)
{
    const int idx = blockIdx.x*256 + threadIdx.x;
    if (idx >= 512*(HW/4)) return;
    const int pq  = idx % (HW/4);             // pixel quad 0..143
    const int ch  = idx / (HW/4);             // 0..511
    const int i = ch >> 5, q = (ch >> 4) & 1, cg = ch & 15;

    const float* a0 = g_aff + (i*Bsz + 0)*G;              // warp-uniform
    const float* a1 = g_aff + (i*Bsz + 1)*G;
    const float4* h = (const float4*)(g_h1 + ((i*Bsz + q)*C + cg)*HW) + pq;
    float4 s0 = make_float4(0.f,0.f,0.f,0.f), s1 = s0;
    #pragma unroll
    for (int kk = 0; kk < 16; kk++) {
        float4 hv = __ldg(h + kk*16*(HW/4));
        float w0 = a0[kk], w1 = a1[kk];
        s0.x = fmaf(w0, hv.x, s0.x); s0.y = fmaf(w0, hv.y, s0.y);
        s0.z = fmaf(w0, hv.z, s0.z); s0.w = fmaf(w0, hv.w, s0.w);
        s1.x = fmaf(w1, hv.x, s1.x); s1.y = fmaf(w1, hv.y, s1.y);
        s1.z = fmaf(w1, hv.z, s1.z); s1.w = fmaf(w1, hv.w, s1.w);
    }
    out[ch*(HW/4) + pq]              = s0;   // p = 0
    out[512*(HW/4) + ch*(HW/4) + pq] = s1;   // p = 1
}

// ---------------------------------------------------------------------------
extern "C" void kernel_launch(void* const* d_in, const int* in_sizes, int n_in,
                              void* d_out, int out_size)
{
    const float* x  = (const float*)d_in[0];
    const float* W1 = (const float*)d_in[1];
    const float* g1 = (const float*)d_in[2];
    const float* b1 = (const float*)d_in[3];
    const float* m1 = (const float*)d_in[4];
    const float* v1 = (const float*)d_in[5];
    const float* W2 = (const float*)d_in[6];
    const float* g2 = (const float*)d_in[7];
    const float* b2 = (const float*)d_in[8];
    const float* m2 = (const float*)d_in[9];
    const float* v2 = (const float*)d_in[10];
    float4* out = (float4*)d_out;

    conv1_kernel<<<1024, 192>>>(x, W1, g1, b1, m1, v1);
    conv2_pool_kernel<<<1024, 128>>>(W2, g2, b2, m2, v2);
    aff_kernel<<<64, 256>>>();
    out_kernel<<<(512*(HW/4) + 255)/256, 256>>>(out);
}

// round 12
// speedup vs baseline: 1.1426x; 1.1426x over previous
#include <cuda_runtime.h>

#define G   16
#define Bsz 2
#define C   256
#define Cg  16
#define HW  576     // 24*24
#define AC  6400    // 25*C
#define EPSI 1e-5f

typedef unsigned long long ull;

// Scratch (device globals — no allocation allowed)
__device__ float g_h1[G*Bsz*C*HW];     // (i,b,c,hw)  18.9 MB (L2-resident)
__device__ float g_pooled[G*Bsz*AC];   // (i,b,ac)
__device__ float g_aff[G*Bsz*G];       // aff_i[i,b,l]

// ---- packed f32x2 helpers (sm_103a FFMA2 path, not emitted by ptxas from C++) ----
__device__ __forceinline__ ull pack2(float lo, float hi) {
    ull r; asm("mov.b64 %0, {%1,%2};" : "=l"(r) : "f"(lo), "f"(hi)); return r;
}
__device__ __forceinline__ void unpack2(ull v, float& lo, float& hi) {
    asm("mov.b64 {%0,%1}, %2;" : "=f"(lo), "=f"(hi) : "l"(v));
}
__device__ __forceinline__ ull fma2(ull a, ull b, ull c) {
    ull d; asm("fma.rn.f32x2 %0, %1, %2, %3;" : "=l"(d) : "l"(a), "l"(b), "l"(c));
    return d;
}

// ---------------------------------------------------------------------------
// Kernel 1: 16x grouped 3x3 conv + BN + ReLU -> g_h1   (identical to R7 best)
// Block = (i, b, group k, oc-half h): 1024 blocks, 8 out-channels each.
// ---------------------------------------------------------------------------
__global__ __launch_bounds__(192, 4) void conv1_kernel(
    const float* __restrict__ x,  const float* __restrict__ W1,
    const float* __restrict__ g1, const float* __restrict__ b1,
    const float* __restrict__ m1, const float* __restrict__ v1)
{
    __shared__ __align__(16) float xt[16*676];        // padded 26x26, 43264 B
    __shared__ __align__(8)  float wsh[144*8];        // [(cin*9+tap)*8 + o]
    const int bid = blockIdx.x;
    const int i = bid >> 6, b = (bid >> 5) & 1, k = (bid >> 1) & 15, h = bid & 1;
    const int tid = threadIdx.x;

    // zero padded tile
    float4* xt4 = (float4*)xt;
    for (int idx = tid; idx < 2704; idx += 192)
        xt4[idx] = make_float4(0.f, 0.f, 0.f, 0.f);
    __syncthreads();

    const float* xsrc = x + (b*C + k*16)*HW;          // 16 contiguous channels
    for (int idx = tid; idx < 16*HW; idx += 192) {
        int c = idx / HW, rem = idx - c*HW;
        int y = rem / 24, xx = rem - y*24;
        xt[c*676 + (y + 1)*26 + (xx + 1)] = xsrc[idx];
    }
    const float* wsrc = W1 + (i*C + k*16 + h*8)*144;  // 1152 contiguous floats
    for (int idx = tid; idx < 1152; idx += 192) {
        int o = idx / 144, r = idx - o*144;           // r = cin*9 + tap
        wsh[r*8 + o] = wsrc[idx];
    }
    __syncthreads();

    ull acc2[3][4];
    #pragma unroll
    for (int j = 0; j < 3; j++)
        #pragma unroll
        for (int op = 0; op < 4; op++) acc2[j][op] = 0ull;

    int p[3], pb[3];
    #pragma unroll
    for (int j = 0; j < 3; j++) {
        p[j] = tid + j*192;                 // all < 576
        int py = p[j] / 24, px = p[j] - py*24;
        pb[j] = py*26 + px;                 // padded base
    }

    for (int cin = 0; cin < 16; cin++) {
        const float* tc = xt + cin*676;
        #pragma unroll
        for (int dy = 0; dy < 3; dy++) {
            #pragma unroll
            for (int dx = 0; dx < 3; dx++) {
                ull xp[3];
                #pragma unroll
                for (int j = 0; j < 3; j++) {
                    float xv = tc[pb[j] + dy*26 + dx];   // immediate-offset LDS
                    xp[j] = pack2(xv, xv);
                }
                const ull* wrow = (const ull*)&wsh[(cin*9 + dy*3 + dx)*8];
                #pragma unroll
                for (int op = 0; op < 4; op++) {
                    ull wv = wrow[op];                   // broadcast LDS.64
                    #pragma unroll
                    for (int j = 0; j < 3; j++)
                        acc2[j][op] = fma2(xp[j], wv, acc2[j][op]);
                }
            }
        }
    }

    float* dst = g_h1 + ((i*Bsz + b)*C + k*16 + h*8)*HW;
    #pragma unroll
    for (int op = 0; op < 4; op++) {
        float a0[3], a1[3];
        #pragma unroll
        for (int j = 0; j < 3; j++) unpack2(acc2[j][op], a0[j], a1[j]);
        #pragma unroll
        for (int half = 0; half < 2; half++) {
            const int o = op*2 + half;
            const int pi = i*C + k*16 + h*8 + o;
            const float s  = g1[pi] * rsqrtf(v1[pi] + EPSI);
            const float cc = fmaf(-m1[pi], s, b1[pi]);
            #pragma unroll
            for (int j = 0; j < 3; j++) {
                float av = half ? a1[j] : a0[j];
                dst[o*HW + p[j]] = fmaxf(fmaf(av, s, cc), 0.f);
            }
        }
    }
}

// ---------------------------------------------------------------------------
// Kernel 2: fused 1x1 grouped conv (pad=1!) + BN + ReLU + 26x26 spatial mean.
// R7 structure, but each lane owns a PIXEL QUAD via LDS.128 (two f32x2 pairs)
// -> 16 LDS.128 : 128 FFMA2 per iter, 2 independent chains per channel.
// 576 px = 4 quad-iters (512) + 1 pair-iter (64).
// ---------------------------------------------------------------------------
__global__ __launch_bounds__(128) void conv2_pool_kernel(
    const float* __restrict__ W2, const float* __restrict__ g2,
    const float* __restrict__ b2, const float* __restrict__ m2,
    const float* __restrict__ v2)
{
    __shared__ __align__(16) float tile[16*HW];     // 36 KB
    const int bid = blockIdx.x;
    const int i = bid >> 6, b = (bid >> 5) & 1, k = (bid >> 1) & 15, hh = bid & 1;
    const int tid = threadIdx.x, lane = tid & 31, warp = tid >> 5;

    const float* src = g_h1 + ((i*Bsz + b)*C + k*16)*HW;  // contiguous 9216 floats
    for (int idx = tid; idx < 16*HW; idx += 128) tile[idx] = src[idx];
    __syncthreads();

    float* pooled = g_pooled + (i*Bsz + b)*AC + k*400;
    const int cend = hh*200 + 200;

    for (int cb = hh*200 + warp*4; cb < cend; cb += 16) {
        ull w2[4][16], s2[4], c2[4];
        float cj[4];
        #pragma unroll
        for (int j = 0; j < 4; j++) {
            const int pi = i*AC + k*400 + cb + j;
            const float* wp = W2 + pi*16;
            #pragma unroll
            for (int cin = 0; cin < 16; cin++) {
                float wv = wp[cin];
                w2[j][cin] = pack2(wv, wv);
            }
            float sc = g2[pi] * rsqrtf(v2[pi] + EPSI);
            float cc = fmaf(-m2[pi], sc, b2[pi]);          // b - m*s
            cj[j] = cc;
            s2[j] = pack2(sc, sc);
            c2[j] = pack2(cc, cc);
        }

        float acc[4] = {0.f, 0.f, 0.f, 0.f};

        // 4 quad iterations: pixels [0, 512)
        #pragma unroll 2
        for (int it = 0; it < 4; it++) {
            const int pq4 = (lane + it*32) * 4;
            ull d2[4][2] = {{0,0},{0,0},{0,0},{0,0}};
            #pragma unroll
            for (int cin = 0; cin < 16; cin++) {
                // LDS.128: two packed pairs per lane, conflict-free
                const float4 xf = *(const float4*)&tile[cin*HW + pq4];
                ull xlo, xhi;
                asm("mov.b64 %0, {%2,%3}; mov.b64 %1, {%4,%5};"
                    : "=l"(xlo), "=l"(xhi)
                    : "f"(xf.x), "f"(xf.y), "f"(xf.z), "f"(xf.w));
                #pragma unroll
                for (int j = 0; j < 4; j++) {
                    d2[j][0] = fma2(xlo, w2[j][cin], d2[j][0]);
                    d2[j][1] = fma2(xhi, w2[j][cin], d2[j][1]);
                }
            }
            #pragma unroll
            for (int j = 0; j < 4; j++) {
                ull t0 = fma2(d2[j][0], s2[j], c2[j]);     // BN
                ull t1 = fma2(d2[j][1], s2[j], c2[j]);
                float a0, a1v, a2, a3;
                unpack2(t0, a0, a1v); unpack2(t1, a2, a3);
                acc[j] += fmaxf(a0, 0.f) + fmaxf(a1v, 0.f)
                        + fmaxf(a2, 0.f) + fmaxf(a3, 0.f);
            }
        }
        // remainder pair iteration: pixels [512, 576)
        {
            const int pp2 = 512 + lane*2;
            ull d2[4] = {0,0,0,0};
            #pragma unroll
            for (int cin = 0; cin < 16; cin++) {
                ull xv = *(const ull*)&tile[cin*HW + pp2];
                #pragma unroll
                for (int j = 0; j < 4; j++)
                    d2[j] = fma2(xv, w2[j][cin], d2[j]);
            }
            #pragma unroll
            for (int j = 0; j < 4; j++) {
                ull t = fma2(d2[j], s2[j], c2[j]);
                float lo, hi; unpack2(t, lo, hi);
                acc[j] += fmaxf(lo, 0.f) + fmaxf(hi, 0.f);
            }
        }

        #pragma unroll
        for (int j = 0; j < 4; j++) {
            float a = acc[j];
            #pragma unroll
            for (int off = 16; off; off >>= 1)
                a += __shfl_xor_sync(0xffffffffu, a, off);
            if (lane == 0) {
                // 100 border pixels of the (pad=1) 26x26 conv output
                float border = 100.f * fmaxf(cj[j], 0.f);
                pooled[cb + j] = (a + border) * (1.f / 676.f);
            }
        }
    }
}

// ---------------------------------------------------------------------------
// aff_i[i,b,l] = <pooled[i,b,i*400:..], pooled[i,b,l*400:..]>/16
// ---------------------------------------------------------------------------
__global__ __launch_bounds__(256) void aff_kernel()
{
    const int gw = blockIdx.x*8 + (threadIdx.x >> 5);   // 0..511
    const int lane = threadIdx.x & 31;
    const int i = gw >> 5, b = (gw >> 4) & 1, l = gw & 15;
    const float* base = g_pooled + (i*Bsz + b)*AC;
    const float* pa = base + i*400;
    const float* pb = base + l*400;
    float s = 0.f;
    #pragma unroll
    for (int m3 = lane; m3 < 400; m3 += 32)
        s = fmaf(pa[m3], pb[m3], s);
    #pragma unroll
    for (int off = 16; off; off >>= 1)
        s += __shfl_xor_sync(0xffffffffu, s, off);
    if (lane == 0) g_aff[(i*Bsz + b)*G + l] = s * (1.f / 16.f);
}

// ---------------------------------------------------------------------------
// z: float2 pixel pairs (R7 best variant)
// ---------------------------------------------------------------------------
__global__ __launch_bounds__(256) void out_kernel(float2* __restrict__ out)
{
    const int idx = blockIdx.x*256 + threadIdx.x;
    if (idx >= 512*(HW/2)) return;
    const int pp2 = idx % (HW/2);             // pixel pair 0..287
    const int ch  = idx / (HW/2);             // 0..511
    const int i = ch >> 5, q = (ch >> 4) & 1, cg = ch & 15;

    const float* a0 = g_aff + (i*Bsz + 0)*G;              // warp-uniform
    const float* a1 = g_aff + (i*Bsz + 1)*G;
    const float2* h = (const float2*)(g_h1 + ((i*Bsz + q)*C + cg)*HW) + pp2;
    float2 s0 = make_float2(0.f, 0.f), s1 = make_float2(0.f, 0.f);
    #pragma unroll
    for (int kk = 0; kk < 16; kk++) {
        float2 hv = __ldg(h + kk*16*(HW/2));
        float w0 = a0[kk], w1 = a1[kk];
        s0.x = fmaf(w0, hv.x, s0.x); s0.y = fmaf(w0, hv.y, s0.y);
        s1.x = fmaf(w1, hv.x, s1.x); s1.y = fmaf(w1, hv.y, s1.y);
    }
    out[ch*(HW/2) + pp2]              = s0;   // p = 0
    out[512*(HW/2) + ch*(HW/2) + pp2] = s1;   // p = 1
}

// ---------------------------------------------------------------------------
extern "C" void kernel_launch(void* const* d_in, const int* in_sizes, int n_in,
                              void* d_out, int out_size)
{
    const float* x  = (const float*)d_in[0];
    const float* W1 = (const float*)d_in[1];
    const float* g1 = (const float*)d_in[2];
    const float* b1 = (const float*)d_in[3];
    const float* m1 = (const float*)d_in[4];
    const float* v1 = (const float*)d_in[5];
    const float* W2 = (const float*)d_in[6];
    const float* g2 = (const float*)d_in[7];
    const float* b2 = (const float*)d_in[8];
    const float* m2 = (const float*)d_in[9];
    const float* v2 = (const float*)d_in[10];
    float2* out = (float2*)d_out;

    conv1_kernel<<<1024, 192>>>(x, W1, g1, b1, m1, v1);
    conv2_pool_kernel<<<1024, 128>>>(W2, g2, b2, m2, v2);
    aff_kernel<<<64, 256>>>();
    out_kernel<<<(512*(HW/2) + 255)/256, 256>>>(out);
}